// round 15
// baseline (speedup 1.0000x reference)
#include <cuda_runtime.h>
#include <cuda_bf16.h>
#include <math.h>
#include <stdint.h>

#define Bb 8
#define Nn 4096
#define Dd 128
#define Hh 8
#define DHh 16
#define FFf 512
#define Kk 16
#define Ll 2

// ---------------- scratch (static device globals; no allocations) ----------
__device__ float g_feat[Bb * Nn * Dd];
__device__ float g_h[Bb * Nn * Dd];
__device__ int   g_knn[Bb * Nn * Kk];
__device__ float g_pooled[Bb * Dd];
__device__ float g_poolpart[Bb * 16 * Dd];
__device__ float4 g_xyz4[Bb * Nn];
__device__ __nv_bfloat16 g_hbf[Bb * Nn * Dd];
__device__ __nv_bfloat16 g_attnbf[Bb * Nn * Dd];
__device__ __nv_bfloat16 g_ffbf[Bb * Nn * FFf];
__device__ __nv_bfloat16 g_qbf[Bb * Hh * Nn * DHh];
__device__ __nv_bfloat16 g_kbf[Bb * Hh * Nn * DHh];
__device__ __nv_bfloat16 g_vtbf[Bb * Hh * DHh * Nn];

// ---------------- helpers ---------------------------------------------------
__device__ __forceinline__ void mma16816(float* d, unsigned a0, unsigned a1,
                                         unsigned a2, unsigned a3,
                                         unsigned b0, unsigned b1) {
    asm volatile(
        "mma.sync.aligned.m16n8k16.row.col.f32.bf16.bf16.f32 "
        "{%0,%1,%2,%3}, {%4,%5,%6,%7}, {%8,%9}, {%0,%1,%2,%3};"
        : "+f"(d[0]), "+f"(d[1]), "+f"(d[2]), "+f"(d[3])
        : "r"(a0), "r"(a1), "r"(a2), "r"(a3), "r"(b0), "r"(b1));
}

// ---------------- embed -----------------------------------------------------
__global__ void embed_kernel(const float* __restrict__ x,
                             const float* __restrict__ xyz_w, const float* __restrict__ xyz_b,
                             const float* __restrict__ ohe_w, const float* __restrict__ ohe_b) {
    int i = blockIdx.x * blockDim.x + threadIdx.x;
    if (i >= Bb * Nn * Dd) return;
    int d = i & (Dd - 1);
    int bn = i >> 7;
    const float* xr = x + (size_t)bn * 8;
    float acc = xyz_b[d] + ohe_b[d];
#pragma unroll
    for (int j = 0; j < 3; j++) acc += xr[j] * xyz_w[d * 3 + j];
#pragma unroll
    for (int j = 0; j < 5; j++) acc += xr[3 + j] * ohe_w[d * 5 + j];
    g_feat[i] = acc;
}

// ---------------- pack xyz into float4 for knn ------------------------------
__global__ void pack_xyz_kernel(const float* __restrict__ x) {
    int i = blockIdx.x * 256 + threadIdx.x;
    if (i >= Bb * Nn) return;
    float4 v = *(const float4*)(x + (size_t)i * 8);
    g_xyz4[i] = make_float4(v.x, v.y, v.z, 0.f);
}

// ---------------- exact KNN: incremental argmin, 2 queries/block ------------
__global__ void knn_select_kernel() {
    int b = blockIdx.y, n0 = blockIdx.x * 2;
    int tid = threadIdx.x;
    __shared__ float d2s[2][Nn];
    __shared__ unsigned long long wred[2][4];
    const float4* xb = g_xyz4 + (size_t)b * Nn;
    float4 qa = xb[n0];
    float4 qb = xb[n0 + 1];
    for (int j = tid; j < Nn; j += 256) {
        float4 r = xb[j];
        float dxa = r.x - qa.x, dya = r.y - qa.y, dza = r.z - qa.z;
        float dxb = r.x - qb.x, dyb = r.y - qb.y, dzb = r.z - qb.z;
        d2s[0][j] = dxa * dxa + dya * dya + dza * dza;
        d2s[1][j] = dxb * dxb + dyb * dyb + dzb * dzb;
    }
    __syncthreads();
    int g = tid >> 7, gtid = tid & 127;
    int lane = tid & 31, warp = gtid >> 5;
    float* d2 = d2s[g];
    int barid = g + 1;

    unsigned long long best = 0xFFFFFFFFFFFFFFFFull;
#pragma unroll 8
    for (int p = 0; p < 32; p++) {
        int j = gtid + p * 128;
        unsigned long long key =
            ((unsigned long long)__float_as_uint(d2[j]) << 32) | (unsigned)j;
        best = best < key ? best : key;
    }

    for (int it = 0; it <= Kk; ++it) {
        unsigned long long wb = best;
#pragma unroll
        for (int o = 16; o > 0; o >>= 1) {
            unsigned long long other = __shfl_xor_sync(0xffffffffu, wb, o);
            wb = wb < other ? wb : other;
        }
        if (lane == 0) wred[g][warp] = wb;
        asm volatile("bar.sync %0, %1;" :: "r"(barid), "r"(128) : "memory");
        unsigned long long gb = wred[g][0];
#pragma unroll
        for (int w = 1; w < 4; w++) gb = gb < wred[g][w] ? gb : wred[g][w];
        int sel = (int)(gb & 0xFFFFFFFFu);
        if (it > 0 && gtid == 0)
            g_knn[((size_t)b * Nn + n0 + g) * Kk + (it - 1)] = sel;
        if ((sel & 127) == gtid) {
            d2[sel] = __int_as_float(0x7F800000);
            best = 0xFFFFFFFFFFFFFFFFull;
#pragma unroll 8
            for (int p = 0; p < 32; p++) {
                int j = gtid + p * 128;
                unsigned long long key =
                    ((unsigned long long)__float_as_uint(d2[j]) << 32) | (unsigned)j;
                best = best < key ? best : key;
            }
        }
        asm volatile("bar.sync %0, %1;" :: "r"(barid), "r"(128) : "memory");
    }
}

// ---------------- KNN attention: one warp per (b,n); writes h + hbf --------
__global__ void knn_attn_kernel() {
    int gw = (blockIdx.x * blockDim.x + threadIdx.x) >> 5;
    int lane = threadIdx.x & 31;
    if (gw >= Bb * Nn) return;
    int b = gw >> 12;
    int n = gw & (Nn - 1);
    const float* fb = g_feat + (size_t)b * Nn * Dd;
    const float* qr = fb + (size_t)n * Dd;
    float q0 = qr[lane], q1 = qr[lane + 32], q2 = qr[lane + 64], q3 = qr[lane + 96];
    const int* idxp = g_knn + (size_t)gw * Kk;
    int idx[Kk];
#pragma unroll
    for (int k = 0; k < Kk; k++) idx[k] = idxp[k];
    float sc[Kk];
    const float scale = 0.08838834764831845f;
#pragma unroll
    for (int k = 0; k < Kk; k++) {
        const float* fr = fb + (size_t)idx[k] * Dd;
        float p = q0 * fr[lane] + q1 * fr[lane + 32] + q2 * fr[lane + 64] + q3 * fr[lane + 96];
#pragma unroll
        for (int o = 16; o > 0; o >>= 1) p += __shfl_xor_sync(0xffffffffu, p, o);
        sc[k] = p * scale;
    }
    float m = sc[0];
#pragma unroll
    for (int k = 1; k < Kk; k++) m = fmaxf(m, sc[k]);
    float l = 0.f;
#pragma unroll
    for (int k = 0; k < Kk; k++) { sc[k] = __expf(sc[k] - m); l += sc[k]; }
    float inv = 1.f / l;
    float o0 = 0.f, o1 = 0.f, o2 = 0.f, o3 = 0.f;
#pragma unroll
    for (int k = 0; k < Kk; k++) {
        float w = sc[k] * inv;
        const float* fr = fb + (size_t)idx[k] * Dd;
        o0 += w * fr[lane];
        o1 += w * fr[lane + 32];
        o2 += w * fr[lane + 64];
        o3 += w * fr[lane + 96];
    }
    size_t base = (size_t)(b * Nn + n) * Dd;
    g_h[base + lane] = o0; g_h[base + lane + 32] = o1;
    g_h[base + lane + 64] = o2; g_h[base + lane + 96] = o3;
    g_hbf[base + lane] = __float2bfloat16(o0);
    g_hbf[base + lane + 32] = __float2bfloat16(o1);
    g_hbf[base + lane + 64] = __float2bfloat16(o2);
    g_hbf[base + lane + 96] = __float2bfloat16(o3);
}

// ---------------- bf16 tensor-core GEMM (128x64 tile) -----------------------
#define GMODE_RELU 1
#define GMODE_QKV  2

__device__ __forceinline__ void qkv_store(int m, int n, float v0, float v1) {
    int b = m >> 12, tok = m & (Nn - 1);
    if (n < 128) {
        int hh = n >> 4, dd = n & 15;
        const float s = 0.25f * 1.44269504f;
        __nv_bfloat162 q = __floats2bfloat162_rn(v0 * s, v1 * s);
        *(__nv_bfloat162*)&g_qbf[(((size_t)(b * Hh + hh) * Nn) + tok) * DHh + dd] = q;
    } else if (n < 256) {
        int d = n - 128, hh = d >> 4, dd = d & 15;
        __nv_bfloat162 k2 = __floats2bfloat162_rn(v0, v1);
        *(__nv_bfloat162*)&g_kbf[(((size_t)(b * Hh + hh) * Nn) + tok) * DHh + dd] = k2;
    } else {
        int d = n - 256, hh = d >> 4, dd = d & 15;
        size_t base = ((size_t)(b * Hh + hh) * DHh + dd) * Nn + tok;
        g_vtbf[base] = __float2bfloat16(v0);
        g_vtbf[base + Nn] = __float2bfloat16(v1);
    }
}

__global__ void gemm_bf16_kernel(const __nv_bfloat16* __restrict__ A,
                                 const float* __restrict__ W,
                                 const float* __restrict__ bias,
                                 __nv_bfloat16* __restrict__ Cbf,
                                 int M, int Nd, int Kd, int mode) {
    __shared__ __nv_bfloat16 As[128][72];
    __shared__ __nv_bfloat16 Ws[64][72];
    int tid = threadIdx.x, warp = tid >> 5, lane = tid & 31;
    int m0 = blockIdx.y * 128, n0 = blockIdx.x * 64;
    int mw = (warp & 3) * 32, nw = (warp >> 2) * 32;
    int r = lane >> 2, c = lane & 3;
    float acc[2][4][4] = {};

    for (int k0 = 0; k0 < Kd; k0 += 64) {
        {
            int row = tid >> 1;
            int colb = (tid & 1) * 32;
            const __nv_bfloat16* ap = A + (size_t)(m0 + row) * Kd + k0 + colb;
#pragma unroll
            for (int i = 0; i < 4; i++)
                *(uint4*)&As[row][colb + i * 8] = *(const uint4*)(ap + i * 8);
        }
        {
            int row = tid >> 2;
            int colb = (tid & 3) * 16;
            const float* wp = W + (size_t)(n0 + row) * Kd + k0 + colb;
#pragma unroll
            for (int j = 0; j < 4; j++) {
                float4 f = *(const float4*)(wp + j * 4);
                __nv_bfloat162 lo = __floats2bfloat162_rn(f.x, f.y);
                __nv_bfloat162 hi = __floats2bfloat162_rn(f.z, f.w);
                *(__nv_bfloat162*)&Ws[row][colb + j * 4] = lo;
                *(__nv_bfloat162*)&Ws[row][colb + j * 4 + 2] = hi;
            }
        }
        __syncthreads();
#pragma unroll
        for (int ks = 0; ks < 4; ks++) {
            int kk = ks * 16;
            unsigned a[2][4], bf[4][2];
#pragma unroll
            for (int mi = 0; mi < 2; mi++) {
                a[mi][0] = *(unsigned*)&As[mw + mi * 16 + r][kk + 2 * c];
                a[mi][1] = *(unsigned*)&As[mw + mi * 16 + r + 8][kk + 2 * c];
                a[mi][2] = *(unsigned*)&As[mw + mi * 16 + r][kk + 2 * c + 8];
                a[mi][3] = *(unsigned*)&As[mw + mi * 16 + r + 8][kk + 2 * c + 8];
            }
#pragma unroll
            for (int ni = 0; ni < 4; ni++) {
                bf[ni][0] = *(unsigned*)&Ws[nw + ni * 8 + r][kk + 2 * c];
                bf[ni][1] = *(unsigned*)&Ws[nw + ni * 8 + r][kk + 2 * c + 8];
            }
#pragma unroll
            for (int mi = 0; mi < 2; mi++)
#pragma unroll
                for (int ni = 0; ni < 4; ni++)
                    mma16816(acc[mi][ni], a[mi][0], a[mi][1], a[mi][2], a[mi][3],
                             bf[ni][0], bf[ni][1]);
        }
        __syncthreads();
    }

#pragma unroll
    for (int mi = 0; mi < 2; mi++) {
#pragma unroll
        for (int ni = 0; ni < 4; ni++) {
            int n = n0 + nw + ni * 8 + 2 * c;
            float b0 = bias[n], b1 = bias[n + 1];
            int mA = m0 + mw + mi * 16 + r;
            int mB = mA + 8;
            float v0 = acc[mi][ni][0] + b0, v1 = acc[mi][ni][1] + b1;
            float v2 = acc[mi][ni][2] + b0, v3 = acc[mi][ni][3] + b1;
            if (mode == GMODE_RELU) {
                __nv_bfloat162 x0 = __floats2bfloat162_rn(fmaxf(v0, 0.f), fmaxf(v1, 0.f));
                __nv_bfloat162 x1 = __floats2bfloat162_rn(fmaxf(v2, 0.f), fmaxf(v3, 0.f));
                *(__nv_bfloat162*)&Cbf[(size_t)mA * Nd + n] = x0;
                *(__nv_bfloat162*)&Cbf[(size_t)mB * Nd + n] = x1;
            } else {
                qkv_store(mA, n, v0, v1);
                qkv_store(mB, n, v2, v3);
            }
        }
    }
}

// ---------------- fused GEMM(Nd=128) + residual + LayerNorm -----------------
// tile 64M x 128N, 8 warps = 2M x 4N of 32x32 warp tiles. Epilogue:
// v = acc + bias + h_old; row-wise LN; writes h(fp32) + hbf(bf16).
__global__ __launch_bounds__(256, 2)
void gemm_ln_kernel(const __nv_bfloat16* __restrict__ A,
                    const float* __restrict__ W,
                    const float* __restrict__ bias,
                    const float* __restrict__ lnw,
                    const float* __restrict__ lnb,
                    int Kd) {
    __shared__ __nv_bfloat16 As[64][72];
    __shared__ __nv_bfloat16 Ws[128][72];
    __shared__ float ssum[64][4];
    __shared__ float ssq[64][4];
    int tid = threadIdx.x, warp = tid >> 5, lane = tid & 31;
    int m0 = blockIdx.x * 64;
    int nwarp = warp & 3, mwarp = warp >> 2;
    int nw = nwarp * 32, mw = mwarp * 32;
    int r = lane >> 2, c = lane & 3;
    float acc[2][4][4] = {};

    for (int k0 = 0; k0 < Kd; k0 += 64) {
        {
            int row = tid >> 2;
            int colb = (tid & 3) * 16;
            const __nv_bfloat16* ap = A + (size_t)(m0 + row) * Kd + k0 + colb;
#pragma unroll
            for (int i = 0; i < 2; i++)
                *(uint4*)&As[row][colb + i * 8] = *(const uint4*)(ap + i * 8);
        }
        {
            int row = tid >> 1;
            int colb = (tid & 1) * 32;
            const float* wp = W + (size_t)row * Kd + k0 + colb;
#pragma unroll
            for (int j = 0; j < 8; j++) {
                float4 f = *(const float4*)(wp + j * 4);
                __nv_bfloat162 lo = __floats2bfloat162_rn(f.x, f.y);
                __nv_bfloat162 hi = __floats2bfloat162_rn(f.z, f.w);
                *(__nv_bfloat162*)&Ws[row][colb + j * 4] = lo;
                *(__nv_bfloat162*)&Ws[row][colb + j * 4 + 2] = hi;
            }
        }
        __syncthreads();
#pragma unroll
        for (int ks = 0; ks < 4; ks++) {
            int kk = ks * 16;
            unsigned a[2][4], bf[4][2];
#pragma unroll
            for (int mi = 0; mi < 2; mi++) {
                a[mi][0] = *(unsigned*)&As[mw + mi * 16 + r][kk + 2 * c];
                a[mi][1] = *(unsigned*)&As[mw + mi * 16 + r + 8][kk + 2 * c];
                a[mi][2] = *(unsigned*)&As[mw + mi * 16 + r][kk + 2 * c + 8];
                a[mi][3] = *(unsigned*)&As[mw + mi * 16 + r + 8][kk + 2 * c + 8];
            }
#pragma unroll
            for (int ni = 0; ni < 4; ni++) {
                bf[ni][0] = *(unsigned*)&Ws[nw + ni * 8 + r][kk + 2 * c];
                bf[ni][1] = *(unsigned*)&Ws[nw + ni * 8 + r][kk + 2 * c + 8];
            }
#pragma unroll
            for (int mi = 0; mi < 2; mi++)
#pragma unroll
                for (int ni = 0; ni < 4; ni++)
                    mma16816(acc[mi][ni], a[mi][0], a[mi][1], a[mi][2], a[mi][3],
                             bf[ni][0], bf[ni][1]);
        }
        __syncthreads();
    }

    // epilogue: v = acc + bias + h_old ; per-row stats
    float v[2][4][4];
    float rsum[2][2] = {}, rsq[2][2] = {};
#pragma unroll
    for (int mi = 0; mi < 2; mi++) {
#pragma unroll
        for (int ni = 0; ni < 4; ni++) {
            int n = nw + ni * 8 + 2 * c;
            float b0 = bias[n], b1 = bias[n + 1];
            int mA = m0 + mw + mi * 16 + r;
            float2 hA = *(const float2*)&g_h[(size_t)mA * Dd + n];
            float2 hB = *(const float2*)&g_h[(size_t)(mA + 8) * Dd + n];
            float v0 = acc[mi][ni][0] + b0 + hA.x;
            float v1 = acc[mi][ni][1] + b1 + hA.y;
            float v2 = acc[mi][ni][2] + b0 + hB.x;
            float v3 = acc[mi][ni][3] + b1 + hB.y;
            v[mi][ni][0] = v0; v[mi][ni][1] = v1;
            v[mi][ni][2] = v2; v[mi][ni][3] = v3;
            rsum[mi][0] += v0 + v1; rsq[mi][0] += v0 * v0 + v1 * v1;
            rsum[mi][1] += v2 + v3; rsq[mi][1] += v2 * v2 + v3 * v3;
        }
    }
#pragma unroll
    for (int mi = 0; mi < 2; mi++) {
#pragma unroll
        for (int hrow = 0; hrow < 2; hrow++) {
            float s = rsum[mi][hrow], q = rsq[mi][hrow];
            s += __shfl_xor_sync(0xffffffffu, s, 1);
            s += __shfl_xor_sync(0xffffffffu, s, 2);
            q += __shfl_xor_sync(0xffffffffu, q, 1);
            q += __shfl_xor_sync(0xffffffffu, q, 2);
            if (c == 0) {
                int row = mw + mi * 16 + hrow * 8 + r;
                ssum[row][nwarp] = s;
                ssq[row][nwarp] = q;
            }
        }
    }
    __syncthreads();
#pragma unroll
    for (int mi = 0; mi < 2; mi++) {
#pragma unroll
        for (int hrow = 0; hrow < 2; hrow++) {
            int row = mw + mi * 16 + hrow * 8 + r;
            float S = ssum[row][0] + ssum[row][1] + ssum[row][2] + ssum[row][3];
            float Q = ssq[row][0] + ssq[row][1] + ssq[row][2] + ssq[row][3];
            float mean = S * (1.f / Dd);
            float var = Q * (1.f / Dd) - mean * mean;
            float inv = rsqrtf(var + 1e-5f);
            size_t gbase = (size_t)(m0 + row) * Dd;
#pragma unroll
            for (int ni = 0; ni < 4; ni++) {
                int n = nw + ni * 8 + 2 * c;
                float y0 = (v[mi][ni][hrow * 2] - mean) * inv * lnw[n] + lnb[n];
                float y1 = (v[mi][ni][hrow * 2 + 1] - mean) * inv * lnw[n + 1] + lnb[n + 1];
                *(float2*)&g_h[gbase + n] = make_float2(y0, y1);
                *(__nv_bfloat162*)&g_hbf[gbase + n] = __floats2bfloat162_rn(y0, y1);
            }
        }
    }
}

// ---------------- flash attention: 128-key tiles, 2 compute passes ----------
#define KPITCH 24
#define VPITCH 136

__global__ void flash_mha_kernel() {
    int b = blockIdx.z, h = blockIdx.y;
    int tid = threadIdx.x;
    int warp = tid >> 5, lane = tid & 31;
    int q0 = blockIdx.x * 128 + warp * 16;
    size_t bh = (size_t)b * Hh + h;
    const __nv_bfloat16* qp = g_qbf + bh * Nn * DHh;
    const __nv_bfloat16* kp = g_kbf + bh * Nn * DHh;
    const __nv_bfloat16* vp = g_vtbf + bh * DHh * Nn;

    __shared__ __nv_bfloat16 Ks[128 * KPITCH];
    __shared__ __nv_bfloat16 Vts[16 * VPITCH];

    int r = lane >> 2;
    int c = lane & 3;

    unsigned qa0 = *(const unsigned*)(qp + (size_t)(q0 + r) * 16 + 2 * c);
    unsigned qa1 = *(const unsigned*)(qp + (size_t)(q0 + r + 8) * 16 + 2 * c);
    unsigned qa2 = *(const unsigned*)(qp + (size_t)(q0 + r) * 16 + 2 * c + 8);
    unsigned qa3 = *(const unsigned*)(qp + (size_t)(q0 + r + 8) * 16 + 2 * c + 8);

    float o[2][4] = {};
    float osum[4] = {};
    const unsigned ONES = 0x3F803F80u;

    int krow = tid >> 1, kq = (tid & 1) * 8;
    int vrow = tid >> 4, vcol = (tid & 15) * 8;

    uint4 kreg = *(const uint4*)(kp + (size_t)krow * 16 + kq);
    uint4 vreg = *(const uint4*)(vp + (size_t)vrow * Nn + vcol);

    for (int kt = 0; kt < Nn; kt += 128) {
        *(uint4*)(Ks + krow * KPITCH + kq) = kreg;
        *(uint4*)(Vts + vrow * VPITCH + vcol) = vreg;
        __syncthreads();

        if (kt + 128 < Nn) {
            kreg = *(const uint4*)(kp + (size_t)(kt + 128 + krow) * 16 + kq);
            vreg = *(const uint4*)(vp + (size_t)vrow * Nn + kt + 128 + vcol);
        }

#pragma unroll
        for (int hh = 0; hh < 2; hh++) {
            const __nv_bfloat16* ks = Ks + hh * 64 * KPITCH;
            const __nv_bfloat16* vts = Vts + hh * 64;

            float s[8][4];
#pragma unroll
            for (int t = 0; t < 8; t++) {
                s[t][0] = s[t][1] = s[t][2] = s[t][3] = 0.f;
                unsigned b0 = *(const unsigned*)(ks + (t * 8 + r) * KPITCH + 2 * c);
                unsigned b1 = *(const unsigned*)(ks + (t * 8 + r) * KPITCH + 2 * c + 8);
                mma16816(s[t], qa0, qa1, qa2, qa3, b0, b1);
            }

            unsigned p01[8], p23[8];
#pragma unroll
            for (int t = 0; t < 8; t++) {
                __nv_bfloat162 x01 = __floats2bfloat162_rn(s[t][0], s[t][1]);
                __nv_bfloat162 x23 = __floats2bfloat162_rn(s[t][2], s[t][3]);
                asm("ex2.approx.ftz.bf16x2 %0, %1;" : "=r"(p01[t]) : "r"(*(unsigned*)&x01));
                asm("ex2.approx.ftz.bf16x2 %0, %1;" : "=r"(p23[t]) : "r"(*(unsigned*)&x23));
            }

#pragma unroll
            for (int st = 0; st < 4; st++) {
                unsigned a0 = p01[2 * st];
                unsigned a1 = p23[2 * st];
                unsigned a2 = p01[2 * st + 1];
                unsigned a3 = p23[2 * st + 1];
#pragma unroll
                for (int d = 0; d < 2; d++) {
                    unsigned b0 = *(const unsigned*)(vts + (d * 8 + r) * VPITCH + st * 16 + 2 * c);
                    unsigned b1 = *(const unsigned*)(vts + (d * 8 + r) * VPITCH + st * 16 + 2 * c + 8);
                    mma16816(o[d], a0, a1, a2, a3, b0, b1);
                }
                mma16816(osum, a0, a1, a2, a3, ONES, ONES);
            }
        }
        __syncthreads();
    }

    float inv0 = 1.f / osum[0];
    float inv1 = 1.f / osum[2];
    __nv_bfloat16* op = g_attnbf + ((size_t)b * Nn + q0) * Dd + h * 16;
#pragma unroll
    for (int d = 0; d < 2; d++) {
        __nv_bfloat162 v0 = __floats2bfloat162_rn(o[d][0] * inv0, o[d][1] * inv0);
        __nv_bfloat162 v1 = __floats2bfloat162_rn(o[d][2] * inv1, o[d][3] * inv1);
        *(__nv_bfloat162*)(op + (size_t)r * Dd + d * 8 + 2 * c) = v0;
        *(__nv_bfloat162*)(op + (size_t)(r + 8) * Dd + d * 8 + 2 * c) = v1;
    }
}

// ---------------- mean pool: two-stage deterministic -----------------------
__global__ void pool_part_kernel() {
    int b = blockIdx.x, chunk = blockIdx.y;
    int d = threadIdx.x;
    const float* hp = g_h + ((size_t)b * Nn + chunk * 256) * Dd + d;
    float s = 0.f;
#pragma unroll 8
    for (int n = 0; n < 256; n++) s += hp[(size_t)n * Dd];
    g_poolpart[(b * 16 + chunk) * Dd + d] = s;
}

__global__ void pool_final_kernel() {
    int b = blockIdx.x;
    int d = threadIdx.x;
    float s = 0.f;
#pragma unroll
    for (int c = 0; c < 16; c++) s += g_poolpart[(b * 16 + c) * Dd + d];
    g_pooled[b * Dd + d] = s * (1.f / Nn);
}

// ---------------- final MLP head -------------------------------------------
__global__ void head_kernel(const float* __restrict__ fc1w, const float* __restrict__ fc1b,
                            const float* __restrict__ fc2w, const float* __restrict__ fc2b,
                            float* __restrict__ out) {
    int b = blockIdx.x;
    __shared__ float ps[128];
    float partial = 0.f;
    for (int f = threadIdx.x; f < FFf; f += 128) {
        float s = fc1b[f];
#pragma unroll 4
        for (int d = 0; d < Dd; d++) s += g_pooled[b * Dd + d] * fc1w[f * Dd + d];
        s = fmaxf(s, 0.f);
        partial += s * fc2w[f];
    }
    ps[threadIdx.x] = partial;
    __syncthreads();
    for (int s = 64; s > 0; s >>= 1) {
        if (threadIdx.x < s) ps[threadIdx.x] += ps[threadIdx.x + s];
        __syncthreads();
    }
    if (threadIdx.x == 0) {
        float z = ps[0] + fc2b[0];
        out[b] = 1.f / (1.f + expf(-z));
    }
}

// ---------------- host launcher --------------------------------------------
extern "C" void kernel_launch(void* const* d_in, const int* in_sizes, int n_in,
                              void* d_out, int out_size) {
    const float* x       = (const float*)d_in[0];
    const float* xyz_w   = (const float*)d_in[1];
    const float* xyz_b   = (const float*)d_in[2];
    const float* ohe_w   = (const float*)d_in[3];
    const float* ohe_b   = (const float*)d_in[4];
    const float* in_w    = (const float*)d_in[5];
    const float* in_b    = (const float*)d_in[6];
    const float* out_w   = (const float*)d_in[7];
    const float* out_b   = (const float*)d_in[8];
    const float* ln1_w   = (const float*)d_in[9];
    const float* ln1_b   = (const float*)d_in[10];
    const float* lin1_w  = (const float*)d_in[11];
    const float* lin1_b  = (const float*)d_in[12];
    const float* lin2_w  = (const float*)d_in[13];
    const float* lin2_b  = (const float*)d_in[14];
    const float* ln2_w   = (const float*)d_in[15];
    const float* ln2_b   = (const float*)d_in[16];
    const float* fc1_w   = (const float*)d_in[17];
    const float* fc1_b   = (const float*)d_in[18];
    const float* fc2_w   = (const float*)d_in[19];
    const float* fc2_b   = (const float*)d_in[20];
    float* out = (float*)d_out;

    __nv_bfloat16 *p_hbf, *p_attnbf, *p_ffbf;
    cudaGetSymbolAddress((void**)&p_hbf, g_hbf);
    cudaGetSymbolAddress((void**)&p_attnbf, g_attnbf);
    cudaGetSymbolAddress((void**)&p_ffbf, g_ffbf);

    const int M = Bb * Nn;

    embed_kernel<<<(Bb * Nn * Dd + 255) / 256, 256>>>(x, xyz_w, xyz_b, ohe_w, ohe_b);
    pack_xyz_kernel<<<(Bb * Nn) / 256, 256>>>(x);
    knn_select_kernel<<<dim3(Nn / 2, Bb), 256>>>();
    knn_attn_kernel<<<(Bb * Nn * 32 + 127) / 128, 128>>>();

    for (int l = 0; l < Ll; l++) {
        gemm_bf16_kernel<<<dim3(384 / 64, M / 128), 256>>>(
            p_hbf, in_w + (size_t)l * 384 * 128, in_b + (size_t)l * 384,
            nullptr, M, 384, 128, GMODE_QKV);
        flash_mha_kernel<<<dim3(Nn / 128, Hh, Bb), 256>>>();
        // out-proj + residual + LN1 fused
        gemm_ln_kernel<<<M / 64, 256>>>(
            p_attnbf, out_w + (size_t)l * 128 * 128, out_b + (size_t)l * 128,
            ln1_w + l * 128, ln1_b + l * 128, 128);
        gemm_bf16_kernel<<<dim3(512 / 64, M / 128), 256>>>(
            p_hbf, lin1_w + (size_t)l * 512 * 128, lin1_b + (size_t)l * 512,
            p_ffbf, M, 512, 128, GMODE_RELU);
        // f2 + residual + LN2 fused
        gemm_ln_kernel<<<M / 64, 256>>>(
            p_ffbf, lin2_w + (size_t)l * 128 * 512, lin2_b + (size_t)l * 128,
            ln2_w + l * 128, ln2_b + l * 128, 512);
        add_ln_dummy:;
    }

    pool_part_kernel<<<dim3(Bb, 16), 128>>>();
    pool_final_kernel<<<Bb, Dd>>>();
    head_kernel<<<Bb, 128>>>(fc1_w, fc1_b, fc2_w, fc2_b, out);
}

// round 16
// speedup vs baseline: 1.0693x; 1.0693x over previous
#include <cuda_runtime.h>
#include <cuda_bf16.h>
#include <math.h>
#include <stdint.h>

#define Bb 8
#define Nn 4096
#define Dd 128
#define Hh 8
#define DHh 16
#define FFf 512
#define Kk 16
#define Ll 2

// ---------------- scratch (static device globals; no allocations) ----------
__device__ float g_feat[Bb * Nn * Dd];
__device__ float g_h[Bb * Nn * Dd];
__device__ float g_tmp[Bb * Nn * Dd];
__device__ int   g_knn[Bb * Nn * Kk];
__device__ float g_pooled[Bb * Dd];
__device__ float g_poolpart[Bb * 16 * Dd];
__device__ float4 g_xyz4[Bb * Nn];
__device__ __nv_bfloat16 g_hbf[Bb * Nn * Dd];
__device__ __nv_bfloat16 g_attnbf[Bb * Nn * Dd];
__device__ __nv_bfloat16 g_ffbf[Bb * Nn * FFf];
__device__ __nv_bfloat16 g_qbf[Bb * Hh * Nn * DHh];
__device__ __nv_bfloat16 g_kbf[Bb * Hh * Nn * DHh];
__device__ __nv_bfloat16 g_vtbf[Bb * Hh * DHh * Nn];

// ---------------- helpers ---------------------------------------------------
__device__ __forceinline__ void mma16816(float* d, unsigned a0, unsigned a1,
                                         unsigned a2, unsigned a3,
                                         unsigned b0, unsigned b1) {
    asm volatile(
        "mma.sync.aligned.m16n8k16.row.col.f32.bf16.bf16.f32 "
        "{%0,%1,%2,%3}, {%4,%5,%6,%7}, {%8,%9}, {%0,%1,%2,%3};"
        : "+f"(d[0]), "+f"(d[1]), "+f"(d[2]), "+f"(d[3])
        : "r"(a0), "r"(a1), "r"(a2), "r"(a3), "r"(b0), "r"(b1));
}

// ---------------- embed -----------------------------------------------------
__global__ void embed_kernel(const float* __restrict__ x,
                             const float* __restrict__ xyz_w, const float* __restrict__ xyz_b,
                             const float* __restrict__ ohe_w, const float* __restrict__ ohe_b) {
    int i = blockIdx.x * blockDim.x + threadIdx.x;
    if (i >= Bb * Nn * Dd) return;
    int d = i & (Dd - 1);
    int bn = i >> 7;
    const float* xr = x + (size_t)bn * 8;
    float acc = xyz_b[d] + ohe_b[d];
#pragma unroll
    for (int j = 0; j < 3; j++) acc += xr[j] * xyz_w[d * 3 + j];
#pragma unroll
    for (int j = 0; j < 5; j++) acc += xr[3 + j] * ohe_w[d * 5 + j];
    g_feat[i] = acc;
}

// ---------------- pack xyz into float4 for knn ------------------------------
__global__ void pack_xyz_kernel(const float* __restrict__ x) {
    int i = blockIdx.x * 256 + threadIdx.x;
    if (i >= Bb * Nn) return;
    float4 v = *(const float4*)(x + (size_t)i * 8);
    g_xyz4[i] = make_float4(v.x, v.y, v.z, 0.f);
}

// ---------------- exact KNN: incremental argmin, 2 queries/block ------------
__global__ void knn_select_kernel() {
    int b = blockIdx.y, n0 = blockIdx.x * 2;
    int tid = threadIdx.x;
    __shared__ float d2s[2][Nn];
    __shared__ unsigned long long wred[2][4];
    const float4* xb = g_xyz4 + (size_t)b * Nn;
    float4 qa = xb[n0];
    float4 qb = xb[n0 + 1];
    for (int j = tid; j < Nn; j += 256) {
        float4 r = xb[j];
        float dxa = r.x - qa.x, dya = r.y - qa.y, dza = r.z - qa.z;
        float dxb = r.x - qb.x, dyb = r.y - qb.y, dzb = r.z - qb.z;
        d2s[0][j] = dxa * dxa + dya * dya + dza * dza;
        d2s[1][j] = dxb * dxb + dyb * dyb + dzb * dzb;
    }
    __syncthreads();
    int g = tid >> 7, gtid = tid & 127;
    int lane = tid & 31, warp = gtid >> 5;
    float* d2 = d2s[g];
    int barid = g + 1;

    unsigned long long best = 0xFFFFFFFFFFFFFFFFull;
#pragma unroll 8
    for (int p = 0; p < 32; p++) {
        int j = gtid + p * 128;
        unsigned long long key =
            ((unsigned long long)__float_as_uint(d2[j]) << 32) | (unsigned)j;
        best = best < key ? best : key;
    }

    for (int it = 0; it <= Kk; ++it) {
        unsigned long long wb = best;
#pragma unroll
        for (int o = 16; o > 0; o >>= 1) {
            unsigned long long other = __shfl_xor_sync(0xffffffffu, wb, o);
            wb = wb < other ? wb : other;
        }
        if (lane == 0) wred[g][warp] = wb;
        asm volatile("bar.sync %0, %1;" :: "r"(barid), "r"(128) : "memory");
        unsigned long long gb = wred[g][0];
#pragma unroll
        for (int w = 1; w < 4; w++) gb = gb < wred[g][w] ? gb : wred[g][w];
        int sel = (int)(gb & 0xFFFFFFFFu);
        if (it > 0 && gtid == 0)
            g_knn[((size_t)b * Nn + n0 + g) * Kk + (it - 1)] = sel;
        if ((sel & 127) == gtid) {
            d2[sel] = __int_as_float(0x7F800000);
            best = 0xFFFFFFFFFFFFFFFFull;
#pragma unroll 8
            for (int p = 0; p < 32; p++) {
                int j = gtid + p * 128;
                unsigned long long key =
                    ((unsigned long long)__float_as_uint(d2[j]) << 32) | (unsigned)j;
                best = best < key ? best : key;
            }
        }
        asm volatile("bar.sync %0, %1;" :: "r"(barid), "r"(128) : "memory");
    }
}

// ---------------- KNN attention: one warp per (b,n); writes h + hbf --------
__global__ void knn_attn_kernel() {
    int gw = (blockIdx.x * blockDim.x + threadIdx.x) >> 5;
    int lane = threadIdx.x & 31;
    if (gw >= Bb * Nn) return;
    int b = gw >> 12;
    int n = gw & (Nn - 1);
    const float* fb = g_feat + (size_t)b * Nn * Dd;
    const float* qr = fb + (size_t)n * Dd;
    float q0 = qr[lane], q1 = qr[lane + 32], q2 = qr[lane + 64], q3 = qr[lane + 96];
    const int* idxp = g_knn + (size_t)gw * Kk;
    int idx[Kk];
#pragma unroll
    for (int k = 0; k < Kk; k++) idx[k] = idxp[k];
    float sc[Kk];
    const float scale = 0.08838834764831845f;
#pragma unroll
    for (int k = 0; k < Kk; k++) {
        const float* fr = fb + (size_t)idx[k] * Dd;
        float p = q0 * fr[lane] + q1 * fr[lane + 32] + q2 * fr[lane + 64] + q3 * fr[lane + 96];
#pragma unroll
        for (int o = 16; o > 0; o >>= 1) p += __shfl_xor_sync(0xffffffffu, p, o);
        sc[k] = p * scale;
    }
    float m = sc[0];
#pragma unroll
    for (int k = 1; k < Kk; k++) m = fmaxf(m, sc[k]);
    float l = 0.f;
#pragma unroll
    for (int k = 0; k < Kk; k++) { sc[k] = __expf(sc[k] - m); l += sc[k]; }
    float inv = 1.f / l;
    float o0 = 0.f, o1 = 0.f, o2 = 0.f, o3 = 0.f;
#pragma unroll
    for (int k = 0; k < Kk; k++) {
        float w = sc[k] * inv;
        const float* fr = fb + (size_t)idx[k] * Dd;
        o0 += w * fr[lane];
        o1 += w * fr[lane + 32];
        o2 += w * fr[lane + 64];
        o3 += w * fr[lane + 96];
    }
    size_t base = (size_t)(b * Nn + n) * Dd;
    g_h[base + lane] = o0; g_h[base + lane + 32] = o1;
    g_h[base + lane + 64] = o2; g_h[base + lane + 96] = o3;
    g_hbf[base + lane] = __float2bfloat16(o0);
    g_hbf[base + lane + 32] = __float2bfloat16(o1);
    g_hbf[base + lane + 64] = __float2bfloat16(o2);
    g_hbf[base + lane + 96] = __float2bfloat16(o3);
}

// ---------------- bf16 tensor-core GEMM (128x64 tile) -----------------------
#define GMODE_F32  0
#define GMODE_RELU 1
#define GMODE_QKV  2

__device__ __forceinline__ void qkv_store(int m, int n, float v0, float v1) {
    int b = m >> 12, tok = m & (Nn - 1);
    if (n < 128) {
        int hh = n >> 4, dd = n & 15;
        const float s = 0.25f * 1.44269504f;
        __nv_bfloat162 q = __floats2bfloat162_rn(v0 * s, v1 * s);
        *(__nv_bfloat162*)&g_qbf[(((size_t)(b * Hh + hh) * Nn) + tok) * DHh + dd] = q;
    } else if (n < 256) {
        int d = n - 128, hh = d >> 4, dd = d & 15;
        __nv_bfloat162 k2 = __floats2bfloat162_rn(v0, v1);
        *(__nv_bfloat162*)&g_kbf[(((size_t)(b * Hh + hh) * Nn) + tok) * DHh + dd] = k2;
    } else {
        int d = n - 256, hh = d >> 4, dd = d & 15;
        size_t base = ((size_t)(b * Hh + hh) * DHh + dd) * Nn + tok;
        g_vtbf[base] = __float2bfloat16(v0);
        g_vtbf[base + Nn] = __float2bfloat16(v1);
    }
}

__global__ void gemm_bf16_kernel(const __nv_bfloat16* __restrict__ A,
                                 const float* __restrict__ W,
                                 const float* __restrict__ bias,
                                 float* __restrict__ Cf,
                                 __nv_bfloat16* __restrict__ Cbf,
                                 int M, int Nd, int Kd, int mode) {
    __shared__ __nv_bfloat16 As[128][72];
    __shared__ __nv_bfloat16 Ws[64][72];
    int tid = threadIdx.x, warp = tid >> 5, lane = tid & 31;
    int m0 = blockIdx.y * 128, n0 = blockIdx.x * 64;
    int mw = (warp & 3) * 32, nw = (warp >> 2) * 32;
    int r = lane >> 2, c = lane & 3;
    float acc[2][4][4] = {};

    for (int k0 = 0; k0 < Kd; k0 += 64) {
        {
            int row = tid >> 1;
            int colb = (tid & 1) * 32;
            const __nv_bfloat16* ap = A + (size_t)(m0 + row) * Kd + k0 + colb;
#pragma unroll
            for (int i = 0; i < 4; i++)
                *(uint4*)&As[row][colb + i * 8] = *(const uint4*)(ap + i * 8);
        }
        {
            int row = tid >> 2;
            int colb = (tid & 3) * 16;
            const float* wp = W + (size_t)(n0 + row) * Kd + k0 + colb;
#pragma unroll
            for (int j = 0; j < 4; j++) {
                float4 f = *(const float4*)(wp + j * 4);
                __nv_bfloat162 lo = __floats2bfloat162_rn(f.x, f.y);
                __nv_bfloat162 hi = __floats2bfloat162_rn(f.z, f.w);
                *(__nv_bfloat162*)&Ws[row][colb + j * 4] = lo;
                *(__nv_bfloat162*)&Ws[row][colb + j * 4 + 2] = hi;
            }
        }
        __syncthreads();
#pragma unroll
        for (int ks = 0; ks < 4; ks++) {
            int kk = ks * 16;
            unsigned a[2][4], bf[4][2];
#pragma unroll
            for (int mi = 0; mi < 2; mi++) {
                a[mi][0] = *(unsigned*)&As[mw + mi * 16 + r][kk + 2 * c];
                a[mi][1] = *(unsigned*)&As[mw + mi * 16 + r + 8][kk + 2 * c];
                a[mi][2] = *(unsigned*)&As[mw + mi * 16 + r][kk + 2 * c + 8];
                a[mi][3] = *(unsigned*)&As[mw + mi * 16 + r + 8][kk + 2 * c + 8];
            }
#pragma unroll
            for (int ni = 0; ni < 4; ni++) {
                bf[ni][0] = *(unsigned*)&Ws[nw + ni * 8 + r][kk + 2 * c];
                bf[ni][1] = *(unsigned*)&Ws[nw + ni * 8 + r][kk + 2 * c + 8];
            }
#pragma unroll
            for (int mi = 0; mi < 2; mi++)
#pragma unroll
                for (int ni = 0; ni < 4; ni++)
                    mma16816(acc[mi][ni], a[mi][0], a[mi][1], a[mi][2], a[mi][3],
                             bf[ni][0], bf[ni][1]);
        }
        __syncthreads();
    }

#pragma unroll
    for (int mi = 0; mi < 2; mi++) {
#pragma unroll
        for (int ni = 0; ni < 4; ni++) {
            int n = n0 + nw + ni * 8 + 2 * c;
            float b0 = bias[n], b1 = bias[n + 1];
            int mA = m0 + mw + mi * 16 + r;
            int mB = mA + 8;
            float v0 = acc[mi][ni][0] + b0, v1 = acc[mi][ni][1] + b1;
            float v2 = acc[mi][ni][2] + b0, v3 = acc[mi][ni][3] + b1;
            if (mode == GMODE_F32) {
                *(float2*)&Cf[(size_t)mA * Nd + n] = make_float2(v0, v1);
                *(float2*)&Cf[(size_t)mB * Nd + n] = make_float2(v2, v3);
            } else if (mode == GMODE_RELU) {
                __nv_bfloat162 x0 = __floats2bfloat162_rn(fmaxf(v0, 0.f), fmaxf(v1, 0.f));
                __nv_bfloat162 x1 = __floats2bfloat162_rn(fmaxf(v2, 0.f), fmaxf(v3, 0.f));
                *(__nv_bfloat162*)&Cbf[(size_t)mA * Nd + n] = x0;
                *(__nv_bfloat162*)&Cbf[(size_t)mB * Nd + n] = x1;
            } else {
                qkv_store(mA, n, v0, v1);
                qkv_store(mB, n, v2, v3);
            }
        }
    }
}

// ---------------- flash attention: 32 q-rows/warp, reg-cached K/V frags -----
#define KPITCH 24
#define VPITCH 136

__global__ __launch_bounds__(256, 1)
void flash_mha_kernel() {
    int b = blockIdx.z, h = blockIdx.y;
    int tid = threadIdx.x;
    int warp = tid >> 5, lane = tid & 31;
    int q0 = blockIdx.x * 256 + warp * 32;
    size_t bh = (size_t)b * Hh + h;
    const __nv_bfloat16* qp = g_qbf + bh * Nn * DHh;
    const __nv_bfloat16* kp = g_kbf + bh * Nn * DHh;
    const __nv_bfloat16* vp = g_vtbf + bh * DHh * Nn;

    __shared__ __nv_bfloat16 Ks[128 * KPITCH];
    __shared__ __nv_bfloat16 Vts[16 * VPITCH];

    int r = lane >> 2;
    int c = lane & 3;

    unsigned qa[2][4];
#pragma unroll
    for (int mi = 0; mi < 2; mi++) {
        int qr0 = q0 + mi * 16;
        qa[mi][0] = *(const unsigned*)(qp + (size_t)(qr0 + r) * 16 + 2 * c);
        qa[mi][1] = *(const unsigned*)(qp + (size_t)(qr0 + r + 8) * 16 + 2 * c);
        qa[mi][2] = *(const unsigned*)(qp + (size_t)(qr0 + r) * 16 + 2 * c + 8);
        qa[mi][3] = *(const unsigned*)(qp + (size_t)(qr0 + r + 8) * 16 + 2 * c + 8);
    }

    float o[2][2][4] = {};
    float osum[2][4] = {};
    const unsigned ONES = 0x3F803F80u;

    int krow = tid >> 1, kq = (tid & 1) * 8;
    int vrow = tid >> 4, vcol = (tid & 15) * 8;

    uint4 kreg = *(const uint4*)(kp + (size_t)krow * 16 + kq);
    uint4 vreg = *(const uint4*)(vp + (size_t)vrow * Nn + vcol);

    for (int kt = 0; kt < Nn; kt += 128) {
        *(uint4*)(Ks + krow * KPITCH + kq) = kreg;
        *(uint4*)(Vts + vrow * VPITCH + vcol) = vreg;
        __syncthreads();

        if (kt + 128 < Nn) {
            kreg = *(const uint4*)(kp + (size_t)(kt + 128 + krow) * 16 + kq);
            vreg = *(const uint4*)(vp + (size_t)vrow * Nn + kt + 128 + vcol);
        }

#pragma unroll
        for (int hh = 0; hh < 2; hh++) {
            const __nv_bfloat16* ks = Ks + hh * 64 * KPITCH;
            const __nv_bfloat16* vts = Vts + hh * 64;

            // load K fragments once, reuse for both q halves
            unsigned kf[8][2];
#pragma unroll
            for (int t = 0; t < 8; t++) {
                kf[t][0] = *(const unsigned*)(ks + (t * 8 + r) * KPITCH + 2 * c);
                kf[t][1] = *(const unsigned*)(ks + (t * 8 + r) * KPITCH + 2 * c + 8);
            }
            // load V fragments once
            unsigned vf[4][2][2];
#pragma unroll
            for (int st = 0; st < 4; st++)
#pragma unroll
                for (int d = 0; d < 2; d++) {
                    vf[st][d][0] = *(const unsigned*)(vts + (d * 8 + r) * VPITCH + st * 16 + 2 * c);
                    vf[st][d][1] = *(const unsigned*)(vts + (d * 8 + r) * VPITCH + st * 16 + 2 * c + 8);
                }

#pragma unroll
            for (int qh = 0; qh < 2; qh++) {
                float s[8][4];
#pragma unroll
                for (int t = 0; t < 8; t++) {
                    s[t][0] = s[t][1] = s[t][2] = s[t][3] = 0.f;
                    mma16816(s[t], qa[qh][0], qa[qh][1], qa[qh][2], qa[qh][3],
                             kf[t][0], kf[t][1]);
                }

                unsigned p01[8], p23[8];
#pragma unroll
                for (int t = 0; t < 8; t++) {
                    __nv_bfloat162 x01 = __floats2bfloat162_rn(s[t][0], s[t][1]);
                    __nv_bfloat162 x23 = __floats2bfloat162_rn(s[t][2], s[t][3]);
                    asm("ex2.approx.ftz.bf16x2 %0, %1;" : "=r"(p01[t]) : "r"(*(unsigned*)&x01));
                    asm("ex2.approx.ftz.bf16x2 %0, %1;" : "=r"(p23[t]) : "r"(*(unsigned*)&x23));
                }

#pragma unroll
                for (int st = 0; st < 4; st++) {
                    unsigned a0 = p01[2 * st];
                    unsigned a1 = p23[2 * st];
                    unsigned a2 = p01[2 * st + 1];
                    unsigned a3 = p23[2 * st + 1];
#pragma unroll
                    for (int d = 0; d < 2; d++)
                        mma16816(o[qh][d], a0, a1, a2, a3, vf[st][d][0], vf[st][d][1]);
                    mma16816(osum[qh], a0, a1, a2, a3, ONES, ONES);
                }
            }
        }
        __syncthreads();
    }

#pragma unroll
    for (int qh = 0; qh < 2; qh++) {
        float inv0 = 1.f / osum[qh][0];
        float inv1 = 1.f / osum[qh][2];
        __nv_bfloat16* op = g_attnbf + ((size_t)b * Nn + q0 + qh * 16) * Dd + h * 16;
#pragma unroll
        for (int d = 0; d < 2; d++) {
            __nv_bfloat162 v0 = __floats2bfloat162_rn(o[qh][d][0] * inv0, o[qh][d][1] * inv0);
            __nv_bfloat162 v1 = __floats2bfloat162_rn(o[qh][d][2] * inv1, o[qh][d][3] * inv1);
            *(__nv_bfloat162*)(op + (size_t)r * Dd + d * 8 + 2 * c) = v0;
            *(__nv_bfloat162*)(op + (size_t)(r + 8) * Dd + d * 8 + 2 * c) = v1;
        }
    }
}

// ---------------- fused residual-add + LayerNorm ---------------------------
__global__ void add_ln_kernel(float* __restrict__ h, const float* __restrict__ rsd,
                              const float* __restrict__ w, const float* __restrict__ bg) {
    int row = blockIdx.x * 8 + (threadIdx.x >> 5);
    int lane = threadIdx.x & 31;
    float* hp = h + (size_t)row * Dd;
    const float* rp = rsd + (size_t)row * Dd;
    float v[4];
    float s = 0.f;
#pragma unroll
    for (int i = 0; i < 4; i++) {
        v[i] = hp[lane + 32 * i] + rp[lane + 32 * i];
        s += v[i];
    }
#pragma unroll
    for (int o = 16; o > 0; o >>= 1) s += __shfl_xor_sync(0xffffffffu, s, o);
    float mean = s * (1.f / Dd);
    float var = 0.f;
#pragma unroll
    for (int i = 0; i < 4; i++) {
        float t = v[i] - mean;
        var += t * t;
    }
#pragma unroll
    for (int o = 16; o > 0; o >>= 1) var += __shfl_xor_sync(0xffffffffu, var, o);
    float inv = rsqrtf(var * (1.f / Dd) + 1e-5f);
#pragma unroll
    for (int i = 0; i < 4; i++) {
        float y = (v[i] - mean) * inv * w[lane + 32 * i] + bg[lane + 32 * i];
        hp[lane + 32 * i] = y;
        g_hbf[(size_t)row * Dd + lane + 32 * i] = __float2bfloat16(y);
    }
}

// ---------------- mean pool: two-stage deterministic -----------------------
__global__ void pool_part_kernel() {
    int b = blockIdx.x, chunk = blockIdx.y;
    int d = threadIdx.x;
    const float* hp = g_h + ((size_t)b * Nn + chunk * 256) * Dd + d;
    float s = 0.f;
#pragma unroll 8
    for (int n = 0; n < 256; n++) s += hp[(size_t)n * Dd];
    g_poolpart[(b * 16 + chunk) * Dd + d] = s;
}

__global__ void pool_final_kernel() {
    int b = blockIdx.x;
    int d = threadIdx.x;
    float s = 0.f;
#pragma unroll
    for (int c = 0; c < 16; c++) s += g_poolpart[(b * 16 + c) * Dd + d];
    g_pooled[b * Dd + d] = s * (1.f / Nn);
}

// ---------------- final MLP head -------------------------------------------
__global__ void head_kernel(const float* __restrict__ fc1w, const float* __restrict__ fc1b,
                            const float* __restrict__ fc2w, const float* __restrict__ fc2b,
                            float* __restrict__ out) {
    int b = blockIdx.x;
    __shared__ float ps[128];
    float partial = 0.f;
    for (int f = threadIdx.x; f < FFf; f += 128) {
        float s = fc1b[f];
#pragma unroll 4
        for (int d = 0; d < Dd; d++) s += g_pooled[b * Dd + d] * fc1w[f * Dd + d];
        s = fmaxf(s, 0.f);
        partial += s * fc2w[f];
    }
    ps[threadIdx.x] = partial;
    __syncthreads();
    for (int s = 64; s > 0; s >>= 1) {
        if (threadIdx.x < s) ps[threadIdx.x] += ps[threadIdx.x + s];
        __syncthreads();
    }
    if (threadIdx.x == 0) {
        float z = ps[0] + fc2b[0];
        out[b] = 1.f / (1.f + expf(-z));
    }
}

// ---------------- host launcher --------------------------------------------
extern "C" void kernel_launch(void* const* d_in, const int* in_sizes, int n_in,
                              void* d_out, int out_size) {
    const float* x       = (const float*)d_in[0];
    const float* xyz_w   = (const float*)d_in[1];
    const float* xyz_b   = (const float*)d_in[2];
    const float* ohe_w   = (const float*)d_in[3];
    const float* ohe_b   = (const float*)d_in[4];
    const float* in_w    = (const float*)d_in[5];
    const float* in_b    = (const float*)d_in[6];
    const float* out_w   = (const float*)d_in[7];
    const float* out_b   = (const float*)d_in[8];
    const float* ln1_w   = (const float*)d_in[9];
    const float* ln1_b   = (const float*)d_in[10];
    const float* lin1_w  = (const float*)d_in[11];
    const float* lin1_b  = (const float*)d_in[12];
    const float* lin2_w  = (const float*)d_in[13];
    const float* lin2_b  = (const float*)d_in[14];
    const float* ln2_w   = (const float*)d_in[15];
    const float* ln2_b   = (const float*)d_in[16];
    const float* fc1_w   = (const float*)d_in[17];
    const float* fc1_b   = (const float*)d_in[18];
    const float* fc2_w   = (const float*)d_in[19];
    const float* fc2_b   = (const float*)d_in[20];
    float* out = (float*)d_out;

    float *p_h, *p_tmp;
    __nv_bfloat16 *p_hbf, *p_attnbf, *p_ffbf;
    cudaGetSymbolAddress((void**)&p_h, g_h);
    cudaGetSymbolAddress((void**)&p_tmp, g_tmp);
    cudaGetSymbolAddress((void**)&p_hbf, g_hbf);
    cudaGetSymbolAddress((void**)&p_attnbf, g_attnbf);
    cudaGetSymbolAddress((void**)&p_ffbf, g_ffbf);

    const int M = Bb * Nn;

    embed_kernel<<<(Bb * Nn * Dd + 255) / 256, 256>>>(x, xyz_w, xyz_b, ohe_w, ohe_b);
    pack_xyz_kernel<<<(Bb * Nn) / 256, 256>>>(x);
    knn_select_kernel<<<dim3(Nn / 2, Bb), 256>>>();
    knn_attn_kernel<<<(Bb * Nn * 32 + 127) / 128, 128>>>();

    for (int l = 0; l < Ll; l++) {
        gemm_bf16_kernel<<<dim3(384 / 64, M / 128), 256>>>(
            p_hbf, in_w + (size_t)l * 384 * 128, in_b + (size_t)l * 384,
            nullptr, nullptr, M, 384, 128, GMODE_QKV);
        flash_mha_kernel<<<dim3(Nn / 256, Hh, Bb), 256>>>();
        gemm_bf16_kernel<<<dim3(128 / 64, M / 128), 256>>>(
            p_attnbf, out_w + (size_t)l * 128 * 128, out_b + (size_t)l * 128,
            p_tmp, nullptr, M, 128, 128, GMODE_F32);
        add_ln_kernel<<<M / 8, 256>>>(p_h, p_tmp, ln1_w + l * 128, ln1_b + l * 128);
        gemm_bf16_kernel<<<dim3(512 / 64, M / 128), 256>>>(
            p_hbf, lin1_w + (size_t)l * 512 * 128, lin1_b + (size_t)l * 512,
            nullptr, p_ffbf, M, 512, 128, GMODE_RELU);
        gemm_bf16_kernel<<<dim3(128 / 64, M / 128), 256>>>(
            p_ffbf, lin2_w + (size_t)l * 128 * 512, lin2_b + (size_t)l * 128,
            p_tmp, nullptr, M, 128, 512, GMODE_F32);
        add_ln_kernel<<<M / 8, 256>>>(p_h, p_tmp, ln2_w + l * 128, ln2_b + l * 128);
    }

    pool_part_kernel<<<dim3(Bb, 16), 128>>>();
    pool_final_kernel<<<Bb, Dd>>>();
    head_kernel<<<Bb, 128>>>(fc1_w, fc1_b, fc2_w, fc2_b, out);
}